// round 1
// baseline (speedup 1.0000x reference)
#include <cuda_runtime.h>
#include <cstdint>

// Problem dims
constexpr int BB = 64;    // batch
constexpr int TT = 1024;  // time steps
constexpr int II = 512;   // input dim
constexpr int HH = 1024;  // hidden dim
constexpr int OO = 512;   // output dim

// ---------------- scratch (device globals: allocation-free) ----------------
__device__ float g_z [(size_t)TT * BB * HH];   // z[t][b][h]   256 MB
__device__ float g_zg[(size_t)TT * BB * HH];   // Zg[t][b][h]  256 MB
__device__ float g_hs[(size_t)TT * BB * HH];   // hs[t][b][h]  256 MB
__device__ float g_h [2][BB * HH];             // double-buffered h
__device__ unsigned g_bar  = 0;                // grid barrier counter
__device__ unsigned g_exit = 0;                // reset coordination

// ============================================================================
// Generic NT SGEMM: C[m][n] = sum_k A[m][k] * Bw[n][k] + bias[n]
// MODE 0: A rows interleaved as inputs[b][t][:] with m=(t,b); C contiguous
// MODE 1: A contiguous; C contiguous
// MODE 2: A contiguous; C rows interleaved as outs[b][t][:] with m=(t,b)
// BM=BN=128, BK=8, 256 threads, 8x8 per-thread tile. All dims divide tiles.
// ============================================================================
template <int MODE>
__global__ void __launch_bounds__(256) gemm_nt(
    const float* __restrict__ A, const float* __restrict__ Bw,
    const float* __restrict__ bias, float* __restrict__ C,
    int M, int N, int K, int lda, int ldb)
{
    constexpr int BM = 128, BN = 128, BK = 8;
    __shared__ float As[BK][BM];
    __shared__ float Bs[BK][BN];

    const int tid = threadIdx.x;
    const int bm = blockIdx.y * BM;
    const int bn = blockIdx.x * BN;
    const int tx = tid & 15;   // 0..15
    const int ty = tid >> 4;   // 0..15

    float acc[8][8];
#pragma unroll
    for (int i = 0; i < 8; i++)
#pragma unroll
        for (int j = 0; j < 8; j++) acc[i][j] = 0.f;

    const int lrow = tid >> 1;          // 0..127
    const int lseg = (tid & 1) << 2;    // 0 or 4

    // fixed per-thread row base pointers
    const int am = bm + lrow;
    const float* arow;
    if (MODE == 0) {
        // m = t*BB + b  ->  A + (b*TT + t)*lda
        arow = A + ((size_t)(am & (BB - 1)) * TT + (size_t)(am >> 6)) * lda;
    } else {
        arow = A + (size_t)am * lda;
    }
    const float* brow = Bw + (size_t)(bn + lrow) * ldb;

    for (int k0 = 0; k0 < K; k0 += BK) {
        float4 av = *(const float4*)(arow + k0 + lseg);
        float4 bv = *(const float4*)(brow + k0 + lseg);
        As[lseg + 0][lrow] = av.x; As[lseg + 1][lrow] = av.y;
        As[lseg + 2][lrow] = av.z; As[lseg + 3][lrow] = av.w;
        Bs[lseg + 0][lrow] = bv.x; Bs[lseg + 1][lrow] = bv.y;
        Bs[lseg + 2][lrow] = bv.z; Bs[lseg + 3][lrow] = bv.w;
        __syncthreads();
#pragma unroll
        for (int kk = 0; kk < BK; kk++) {
            float a[8], b[8];
            *(float4*)&a[0] = *(const float4*)&As[kk][ty * 8];
            *(float4*)&a[4] = *(const float4*)&As[kk][ty * 8 + 4];
            *(float4*)&b[0] = *(const float4*)&Bs[kk][tx * 8];
            *(float4*)&b[4] = *(const float4*)&Bs[kk][tx * 8 + 4];
#pragma unroll
            for (int i = 0; i < 8; i++)
#pragma unroll
                for (int j = 0; j < 8; j++) acc[i][j] += a[i] * b[j];
        }
        __syncthreads();
    }

    // epilogue: add bias, store
#pragma unroll
    for (int i = 0; i < 8; i++) {
        const int m = bm + ty * 8 + i;
        float* crow;
        if (MODE == 2) {
            crow = C + ((size_t)(m & (BB - 1)) * TT + (size_t)(m >> 6)) * N;
        } else {
            crow = C + (size_t)m * N;
        }
#pragma unroll
        for (int j0 = 0; j0 < 8; j0 += 4) {
            const int n = bn + tx * 8 + j0;
            float4 o;
            o.x = acc[i][j0 + 0] + bias[n + 0];
            o.y = acc[i][j0 + 1] + bias[n + 1];
            o.z = acc[i][j0 + 2] + bias[n + 2];
            o.w = acc[i][j0 + 3] + bias[n + 3];
            *(float4*)(crow + n) = o;
        }
    }
}

// ============================================================================
// Persistent scan kernel: 1024 sequential steps with software grid barrier.
//   pre[b][j] = sum_k h_prev[b][k] * Wg_h[j][k]
//   u = sigmoid(pre + Zg[t][b][j]);  h_new = u*h_prev + (1-u)*z[t][b][j]
// 128 blocks x 128 threads; block owns 8 j-columns; Wg_h slice in smem.
// ============================================================================
constexpr int NBLK = 128;
constexpr int SCTH = 128;
constexpr int JPB  = HH / NBLK;   // 8 columns per block
constexpr int KC   = 32;          // h chunk width (k dim)
constexpr int HSTR = 44;          // h_c row stride: 44 % 32 == 12 -> conflict-free float4

__device__ __forceinline__ void grid_sync(unsigned gen)
{
    __syncthreads();
    if (threadIdx.x == 0) {
        __threadfence();
        atomicAdd(&g_bar, 1u);
        const unsigned target = gen * (unsigned)NBLK;
        while (*(volatile unsigned*)&g_bar < target) { }
        __threadfence();
    }
    __syncthreads();
}

__global__ void __launch_bounds__(SCTH, 1) scan_kernel(
    const float* __restrict__ W_gate,   // [H][2H], Wg_h = cols [0,H)
    const float* __restrict__ h0,       // [B][H]
    float* __restrict__ out_hfinal)     // [B][H]
{
    __shared__ float W_s[JPB * HH];       // 32 KB, j-major
    __shared__ float h_c[BB * HSTR];      // 11 KB staged h chunk

    const int tid  = threadIdx.x;
    const int blk  = blockIdx.x;
    const int warp = tid >> 5;
    const int lane = tid & 31;
    const int jbase = blk * JPB;

    // load this block's Wg_h slice (once for all 1024 steps)
    for (int idx = tid; idx < JPB * HH; idx += SCTH) {
        const int j = idx >> 10, k = idx & (HH - 1);
        W_s[idx] = W_gate[(size_t)(jbase + j) * (2 * HH) + k];
    }
    // initialize h buffer 0 from input h
    for (int idx = blk * SCTH + tid; idx < BB * HH; idx += NBLK * SCTH)
        g_h[0][idx] = h0[idx];

    grid_sync(1);

    // warp -> (batch half, j quad)
    const int bq = warp & 1;
    const int jq = warp >> 1;
    const int b  = bq * 32 + lane;     // 0..63
    const int j0 = jq * 4;             // local j offset (0 or 4)
    const float* hrow = h_c + b * HSTR;

    const int r  = tid >> 1;           // chunk-load row
    const int cs = (tid & 1) * 16;     // chunk-load col segment

    for (int t = 0; t < TT; t++) {
        const float* hp = g_h[t & 1];
        float* hn = g_h[(t & 1) ^ 1];
        const size_t rowoff = ((size_t)t * BB + b) * HH + jbase + j0;

        // prefetch per-element operands (DRAM latency hidden by compute)
        const float4 zg4 = __ldcg((const float4*)(g_zg + rowoff));
        const float4 z4  = __ldcg((const float4*)(g_z  + rowoff));
        const float4 hp4 = __ldcg((const float4*)(hp + (size_t)b * HH + jbase + j0));

        float acc0 = 0.f, acc1 = 0.f, acc2 = 0.f, acc3 = 0.f;

        for (int c = 0; c < HH / KC; c++) {
            // cooperative stage of h_prev[:, c*KC .. c*KC+31] into smem
            {
                const float4* src = (const float4*)(hp + (size_t)r * HH + c * KC + cs);
                float4* dst = (float4*)(h_c + r * HSTR + cs);
                dst[0] = __ldcg(src + 0);
                dst[1] = __ldcg(src + 1);
                dst[2] = __ldcg(src + 2);
                dst[3] = __ldcg(src + 3);
            }
            __syncthreads();
#pragma unroll
            for (int oct = 0; oct < KC / 8; oct++) {
                const float4 ha = *(const float4*)(hrow + oct * 8);
                const float4 hb = *(const float4*)(hrow + oct * 8 + 4);
#pragma unroll
                for (int jj = 0; jj < 4; jj++) {
                    const float4* wp =
                        (const float4*)(W_s + (size_t)(j0 + jj) * HH + c * KC + oct * 8);
                    const float4 wa = wp[0];
                    const float4 wb = wp[1];
                    float s;
                    s  = ha.x * wa.x; s += ha.y * wa.y; s += ha.z * wa.z; s += ha.w * wa.w;
                    s += hb.x * wb.x; s += hb.y * wb.y; s += hb.z * wb.z; s += hb.w * wb.w;
                    if (jj == 0) acc0 += s;
                    else if (jj == 1) acc1 += s;
                    else if (jj == 2) acc2 += s;
                    else acc3 += s;
                }
            }
            __syncthreads();
        }

        // epilogue: sigmoid gate + convex blend
        float4 hn4;
        {
            float x, u;
            x = acc0 + zg4.x; u = 1.f / (1.f + __expf(-x)); hn4.x = u * hp4.x + (1.f - u) * z4.x;
            x = acc1 + zg4.y; u = 1.f / (1.f + __expf(-x)); hn4.y = u * hp4.y + (1.f - u) * z4.y;
            x = acc2 + zg4.z; u = 1.f / (1.f + __expf(-x)); hn4.z = u * hp4.z + (1.f - u) * z4.z;
            x = acc3 + zg4.w; u = 1.f / (1.f + __expf(-x)); hn4.w = u * hp4.w + (1.f - u) * z4.w;
        }
        *(float4*)(hn + (size_t)b * HH + jbase + j0) = hn4;   // next-step h
        *(float4*)(g_hs + rowoff) = hn4;                      // record for output GEMM
        if (t == TT - 1)
            *(float4*)(out_hfinal + (size_t)b * HH + jbase + j0) = hn4;

        grid_sync((unsigned)t + 2);
    }

    // reset barrier state for the next graph replay (safe: last exiter resets)
    __syncthreads();
    if (tid == 0) {
        const unsigned r2 = atomicAdd(&g_exit, 1u);
        if (r2 == NBLK - 1) {
            g_bar = 0u;
            g_exit = 0u;
            __threadfence();
        }
    }
}

// ============================================================================
// kernel_launch
// ============================================================================
extern "C" void kernel_launch(void* const* d_in, const int* in_sizes, int n_in,
                              void* d_out, int out_size)
{
    (void)in_sizes; (void)n_in; (void)out_size;
    const float* inputs = (const float*)d_in[0];   // [B][T][I]
    const float* h0     = (const float*)d_in[1];   // [B][H]
    const float* W_in   = (const float*)d_in[2];   // [H][I]
    const float* b_in   = (const float*)d_in[3];   // [H]
    const float* W_gate = (const float*)d_in[4];   // [H][2H]
    const float* b_gate = (const float*)d_in[5];   // [H]
    const float* W_out  = (const float*)d_in[6];   // [O][H]
    const float* b_out  = (const float*)d_in[7];   // [O]
    float* out = (float*)d_out;                    // outs [B][T][O] ++ h_final [B][H]

    void *zp, *zgp, *hsp;
    cudaGetSymbolAddress(&zp,  g_z);
    cudaGetSymbolAddress(&zgp, g_zg);
    cudaGetSymbolAddress(&hsp, g_hs);
    float* z  = (float*)zp;
    float* zg = (float*)zgp;
    float* hs = (float*)hsp;

    const int M = TT * BB;

    // K1: z[t][b][h] = inputs[b][t][:] . W_in[h][:] + b_in[h]
    {
        dim3 grid(HH / 128, M / 128);
        gemm_nt<0><<<grid, 256>>>(inputs, W_in, b_in, z, M, HH, II, II, II);
    }
    // K2: Zg[t][b][h] = z[t][b][:] . Wg_z[h][:] + b_gate[h]   (Wg_z = W_gate cols [H,2H))
    {
        dim3 grid(HH / 128, M / 128);
        gemm_nt<1><<<grid, 256>>>(z, W_gate + HH, b_gate, zg, M, HH, HH, HH, 2 * HH);
    }
    // K3: sequential scan (persistent, 1024 grid barriers)
    scan_kernel<<<NBLK, SCTH>>>(W_gate, h0, out + (size_t)BB * TT * OO);

    // K4: outs[b][t][o] = hs[t][b][:] . W_out[o][:] + b_out[o]
    {
        dim3 grid(OO / 128, M / 128);
        gemm_nt<2><<<grid, 256>>>(hs, W_out, b_out, out, M, OO, HH, HH, HH);
    }
}

// round 4
// speedup vs baseline: 1.0183x; 1.0183x over previous
#include <cuda_runtime.h>
#include <cuda_bf16.h>
#include <cstdint>

// Problem dims
constexpr int BB = 64;    // batch
constexpr int TT = 1024;  // time steps
constexpr int II = 512;   // input dim
constexpr int HH = 1024;  // hidden dim
constexpr int OO = 512;   // output dim

// ---------------- scratch (device globals: allocation-free) ----------------
__device__ float          g_z  [(size_t)TT * BB * HH];        // z fp32 (scan)
__device__ float          g_zg [(size_t)TT * BB * HH];        // Zg fp32 (scan)
__device__ __nv_bfloat16  g_z2 [(size_t)TT * BB * 2 * HH];    // z hi|lo (GEMM2 A)
__device__ __nv_bfloat16  g_hs2[(size_t)TT * BB * 2 * HH];    // hs hi|lo (GEMM4 A)
__device__ __nv_bfloat16  g_in2[(size_t)BB * TT * 2 * II];    // inputs hi|lo
__device__ __nv_bfloat16  g_Win2 [(size_t)HH * 2 * II];
__device__ __nv_bfloat16  g_Wgz2 [(size_t)HH * 2 * HH];
__device__ __nv_bfloat16  g_Wout2[(size_t)OO * 2 * HH];
__device__ float          g_h[2][BB * HH];
__device__ unsigned g_bar  = 0;
__device__ unsigned g_exit = 0;

// ============================ PTX helpers ==================================
__device__ __forceinline__ uint32_t smem_u32(const void* p) {
    uint32_t a;
    asm("{ .reg .u64 t; cvta.to.shared.u64 t, %1; cvt.u32.u64 %0, t; }" : "=r"(a) : "l"(p));
    return a;
}
// SW64-style swizzle for 64-byte rows
#define SWZ64(o) ((o) ^ (((o) >> 3) & 0x30))

__device__ __forceinline__ void cp_async16(uint32_t dst, const void* src) {
    asm volatile("cp.async.cg.shared.global [%0], [%1], 16;" :: "r"(dst), "l"(src));
}
#define CP_COMMIT() asm volatile("cp.async.commit_group;" ::: "memory")
template <int N> __device__ __forceinline__ void cp_wait_group() {
    asm volatile("cp.async.wait_group %0;" :: "n"(N) : "memory");
}
__device__ __forceinline__ void ldsm_x4(uint32_t (&r)[4], uint32_t addr) {
    asm volatile("ldmatrix.sync.aligned.m8n8.x4.shared.b16 {%0,%1,%2,%3}, [%4];"
        : "=r"(r[0]), "=r"(r[1]), "=r"(r[2]), "=r"(r[3]) : "r"(addr));
}
__device__ __forceinline__ void mma16816(float (&d)[4], const uint32_t (&a)[4],
                                         uint32_t b0, uint32_t b1) {
    asm volatile("mma.sync.aligned.m16n8k16.row.col.f32.bf16.bf16.f32 "
        "{%0,%1,%2,%3}, {%4,%5,%6,%7}, {%8,%9}, {%0,%1,%2,%3};"
        : "+f"(d[0]), "+f"(d[1]), "+f"(d[2]), "+f"(d[3])
        : "r"(a[0]), "r"(a[1]), "r"(a[2]), "r"(a[3]), "r"(b0), "r"(b1));
}
__device__ __forceinline__ void ffma2(unsigned long long& d, unsigned long long a,
                                      unsigned long long b) {
    asm volatile("fma.rn.f32x2 %0, %1, %2, %0;" : "+l"(d) : "l"(a), "l"(b));
}

// ============================ pack kernels =================================
// fp32 [R, srcld] slice (offset srcoff, width K) -> bf16 [R, 2K]: hi | lo
__global__ void pack_split(const float* __restrict__ src, __nv_bfloat16* __restrict__ dst,
                           int K, int srcld, int srcoff, long total)
{
    for (long i = (long)blockIdx.x * blockDim.x + threadIdx.x; i < total;
         i += (long)gridDim.x * blockDim.x) {
        long r = i / K;
        int  k = (int)(i - r * K);
        float x = src[r * srcld + srcoff + k];
        __nv_bfloat16 hi = __float2bfloat16(x);
        __nv_bfloat16 lo = __float2bfloat16(x - __bfloat162float(hi));
        dst[r * 2 * K + k]     = hi;
        dst[r * 2 * K + K + k] = lo;
    }
}

// ============================ mma.sync GEMM ================================
// 3-term split-precision bf16 GEMM:
//   C = Ahi.Bhi + Ahi.Blo + Alo.Bhi  (+bias)   ~= fp32 A.B to ~2^-17
// A2/B2 rows: [hi(K) | lo(K)] bf16, row length twoK = 2K elements.
// Virtual chunk c in [0, 3*kchunks): phase = c/kchunks selects source regions:
//   phase 0: A hi, B hi;  phase 1: A hi, B lo;  phase 2: A lo, B hi.
// MODE 0: A rows permuted (m=(t,b) -> storage row b*T+t). MODE 2: C rows permuted.
// EMIT: also write bf16 hi|lo of C into Csplit [m][2048] (requires NN==1024).
// BM=BN=128, BK=32, 256 threads (8 warps as 2 row x 4 col, 64x32 warp tile).
constexpr int STAGES = 6;
constexpr int STAGE_BYTES = 16384;           // A 8KB + B 8KB
constexpr int GEMM_SMEM = 1024 + STAGES * STAGE_BYTES;

template <int MODE, bool EMIT>
__global__ void __launch_bounds__(256, 1)
gemm_tc(const __nv_bfloat16* __restrict__ A2, const __nv_bfloat16* __restrict__ B2,
        const float* __restrict__ bias, float* __restrict__ C,
        __nv_bfloat16* __restrict__ Csplit, int twoK, int NN, int kchunks)
{
    extern __shared__ char gsm[];
    const uint32_t sb = (smem_u32(gsm) + 1023u) & ~1023u;   // 1KB-aligned stage base
    const int tid  = threadIdx.x;
    const int wid  = tid >> 5;
    const int lane = tid & 31;
    const int bm = blockIdx.y * 128;
    const int bn = blockIdx.x * 128;
    const int wrow = wid >> 2;   // 0..1  -> m offset *64
    const int wcol = wid & 3;    // 0..3  -> n offset *32
    const int nch = 3 * kchunks;
    const int kbytes = twoK;     // hi-region size in BYTES ( = K elements * 2 )

    // ---- global load slots: i=0,1 A chunks; i=2,3 B chunks (16B each) ----
    const char* gptr[4];
    uint32_t    sptr[4];
#pragma unroll
    for (int i = 0; i < 4; i++) {
        const int idx = (i & 1) ? tid + 256 : tid;   // 0..511
        const int r = idx >> 2, seg = idx & 3;
        if (i < 2) {
            const int am = bm + r;
            const __nv_bfloat16* ar = (MODE == 0)
                ? A2 + ((size_t)(am & (BB - 1)) * TT + (size_t)(am >> 6)) * twoK
                : A2 + (size_t)am * twoK;
            gptr[i] = (const char*)ar + seg * 16;
            sptr[i] = sb + SWZ64((uint32_t)(r * 64 + seg * 16));
        } else {
            gptr[i] = (const char*)(B2 + (size_t)(bn + r) * twoK) + seg * 16;
            sptr[i] = sb + 8192u + SWZ64((uint32_t)(r * 64 + seg * 16));
        }
    }

    auto fill = [&](int cf) {
        const uint32_t soff = (uint32_t)(cf % STAGES) * STAGE_BYTES;
        // phase / k-chunk decomposition
        int phase = 0, kc = cf;
        if (cf >= kchunks)     { phase = 1; kc = cf - kchunks; }
        if (cf >= 2 * kchunks) { phase = 2; kc = cf - 2 * kchunks; }
        const int gA = (phase == 2 ? kbytes : 0) + kc * 64;  // A: hi,hi,lo
        const int gB = (phase == 1 ? kbytes : 0) + kc * 64;  // B: hi,lo,hi
#pragma unroll
        for (int i = 0; i < 2; i++) cp_async16(sptr[i] + soff, gptr[i] + gA);
#pragma unroll
        for (int i = 2; i < 4; i++) cp_async16(sptr[i] + soff, gptr[i] + gB);
        CP_COMMIT();
    };

    // ---- fragment smem addresses (precomputed, swizzled) ----
    uint32_t aAddr[4][2], bAddr[2][2];
    {
        const int lr = lane & 15, lc = lane >> 4;
#pragma unroll
        for (int mt = 0; mt < 4; mt++) {
            const uint32_t rb = (uint32_t)((wrow * 64 + mt * 16 + lr) * 64);
            const uint32_t xv = (rb >> 3) & 0x30;
#pragma unroll
            for (int ks = 0; ks < 2; ks++)
                aAddr[mt][ks] = sb + rb + (((uint32_t)(ks * 32 + lc * 16)) ^ xv);
        }
#pragma unroll
        for (int nb = 0; nb < 2; nb++) {
            const uint32_t rb = (uint32_t)((wcol * 32 + nb * 16 + lr) * 64);
            const uint32_t xv = (rb >> 3) & 0x30;
#pragma unroll
            for (int ks = 0; ks < 2; ks++)
                bAddr[nb][ks] = sb + 8192u + rb + (((uint32_t)(ks * 32 + lc * 16)) ^ xv);
        }
    }

    float acc[4][4][4];
#pragma unroll
    for (int mt = 0; mt < 4; mt++)
#pragma unroll
        for (int nt = 0; nt < 4; nt++)
#pragma unroll
            for (int e = 0; e < 4; e++) acc[mt][nt][e] = 0.f;

    // ---- pipeline ----
#pragma unroll
    for (int c = 0; c < STAGES - 1; c++) fill(c);

    for (int c = 0; c < nch; c++) {
        cp_wait_group<STAGES - 2>();
        __syncthreads();
        if (c + STAGES - 1 < nch) fill(c + STAGES - 1);
        else CP_COMMIT();   // empty group keeps wait_group accounting valid

        const uint32_t soff = (uint32_t)(c % STAGES) * STAGE_BYTES;
#pragma unroll
        for (int ks = 0; ks < 2; ks++) {
            uint32_t a[4][4], b[2][4];
#pragma unroll
            for (int mt = 0; mt < 4; mt++) ldsm_x4(a[mt], aAddr[mt][ks] + soff);
#pragma unroll
            for (int nb = 0; nb < 2; nb++) ldsm_x4(b[nb], bAddr[nb][ks] + soff);
#pragma unroll
            for (int mt = 0; mt < 4; mt++) {
#pragma unroll
                for (int nt = 0; nt < 4; nt++) {
                    const int nb = nt >> 1, hi = nt & 1;
                    mma16816(acc[mt][nt], a[mt], b[nb][hi ? 1 : 0], b[nb][hi ? 3 : 2]);
                }
            }
        }
    }

    // ---- epilogue ----
    const int gid = lane >> 2, tig = lane & 3;
#pragma unroll
    for (int mt = 0; mt < 4; mt++) {
        const int m0 = bm + wrow * 64 + mt * 16 + gid;   // rows m0, m0+8
#pragma unroll
        for (int half = 0; half < 2; half++) {
            const int m = m0 + half * 8;
            float* crow;
            if (MODE == 2)
                crow = C + ((size_t)(m & (BB - 1)) * TT + (size_t)(m >> 6)) * NN;
            else
                crow = C + (size_t)m * NN;
            __nv_bfloat16* srow = EMIT ? (Csplit + (size_t)m * 2048) : nullptr;
#pragma unroll
            for (int nt = 0; nt < 4; nt++) {
                const int n = bn + wcol * 32 + nt * 8 + tig * 2;
                float2 v;
                v.x = acc[mt][nt][half * 2 + 0] + bias[n];
                v.y = acc[mt][nt][half * 2 + 1] + bias[n + 1];
                *(float2*)(crow + n) = v;
                if (EMIT) {
                    __nv_bfloat162 h2, l2;
                    h2.x = __float2bfloat16(v.x);
                    h2.y = __float2bfloat16(v.y);
                    l2.x = __float2bfloat16(v.x - __bfloat162float(h2.x));
                    l2.y = __float2bfloat16(v.y - __bfloat162float(h2.y));
                    *(__nv_bfloat162*)(srow + n)        = h2;
                    *(__nv_bfloat162*)(srow + 1024 + n) = l2;
                }
            }
        }
    }
}

// ============================ scan kernel ==================================
constexpr int NBLK = 128;
constexpr int SCTH = 256;
constexpr int JPB  = HH / NBLK;   // 8 j-columns per block, 2 per thread
constexpr int KC   = 64;          // h chunk width
constexpr int HSTR = 68;          // 68 % 32 == 4 -> conflict-free float4 phases
constexpr int SCAN_SMEM = (JPB * HH + BB * HSTR) * 4;  // 32KB W + 17KB h

__device__ __forceinline__ void grid_sync(unsigned gen)
{
    __syncthreads();
    if (threadIdx.x == 0) {
        __threadfence();
        atomicAdd(&g_bar, 1u);
        const unsigned target = gen * (unsigned)NBLK;
        while (*(volatile unsigned*)&g_bar < target) { }
        __threadfence();
    }
    __syncthreads();
}

__global__ void __launch_bounds__(SCTH, 1) scan_kernel(
    const float* __restrict__ W_gate,   // [H][2H], Wg_h = cols [0,H)
    const float* __restrict__ h0,       // [B][H]
    float* __restrict__ out_hfinal)     // [B][H]
{
    extern __shared__ __align__(16) float smemf[];
    float* W_s = smemf;              // JPB*HH
    float* h_c = smemf + JPB * HH;   // BB*HSTR

    const int tid  = threadIdx.x;
    const int blk  = blockIdx.x;
    const int warp = tid >> 5;
    const int lane = tid & 31;
    const int jbase = blk * JPB;

    for (int idx = tid; idx < JPB * HH; idx += SCTH) {
        const int j = idx >> 10, k = idx & (HH - 1);
        W_s[idx] = W_gate[(size_t)(jbase + j) * (2 * HH) + k];
    }
    for (int idx = blk * SCTH + tid; idx < BB * HH; idx += NBLK * SCTH)
        g_h[0][idx] = h0[idx];

    grid_sync(1);

    const int bq = warp & 1;
    const int jq = warp >> 1;            // 0..3
    const int b  = bq * 32 + lane;       // 0..63
    const int j0 = jq * 2;               // local j (2 per thread)
    const float* hrow = h_c + b * HSTR;

    const int r  = tid & 63;             // staging row
    const int cs = (tid >> 6) * 16;      // staging col segment (floats)

    for (int t = 0; t < TT; t++) {
        const float* hp = g_h[t & 1];
        float* hn = g_h[(t & 1) ^ 1];
        const size_t rowoff = ((size_t)t * BB + b) * HH + jbase + j0;

        const float2 zg2 = __ldcg((const float2*)(g_zg + rowoff));
        const float2 zv2 = __ldcg((const float2*)(g_z  + rowoff));
        const float2 hp2 = __ldcg((const float2*)(hp + (size_t)b * HH + jbase + j0));

        unsigned long long acc0 = 0ull, acc1 = 0ull;

        for (int c = 0; c < HH / KC; c++) {
            {
                const float4* src = (const float4*)(hp + (size_t)r * HH + c * KC + cs);
                float4* dst = (float4*)(h_c + r * HSTR + cs);
                dst[0] = __ldcg(src + 0);
                dst[1] = __ldcg(src + 1);
                dst[2] = __ldcg(src + 2);
                dst[3] = __ldcg(src + 3);
            }
            __syncthreads();
#pragma unroll
            for (int oct = 0; oct < KC / 8; oct++) {
                const ulonglong2 hA = *(const ulonglong2*)(hrow + oct * 8);
                const ulonglong2 hB = *(const ulonglong2*)(hrow + oct * 8 + 4);
                {
                    const float* w = W_s + (size_t)(j0 + 0) * HH + c * KC + oct * 8;
                    const ulonglong2 wA = *(const ulonglong2*)(w);
                    const ulonglong2 wB = *(const ulonglong2*)(w + 4);
                    ffma2(acc0, hA.x, wA.x); ffma2(acc0, hA.y, wA.y);
                    ffma2(acc0, hB.x, wB.x); ffma2(acc0, hB.y, wB.y);
                }
                {
                    const float* w = W_s + (size_t)(j0 + 1) * HH + c * KC + oct * 8;
                    const ulonglong2 wA = *(const ulonglong2*)(w);
                    const ulonglong2 wB = *(const ulonglong2*)(w + 4);
                    ffma2(acc1, hA.x, wA.x); ffma2(acc1, hA.y, wA.y);
                    ffma2(acc1, hB.x, wB.x); ffma2(acc1, hB.y, wB.y);
                }
            }
            __syncthreads();
        }

        float s0, s1;
        {
            uint32_t lo, hi;
            asm("mov.b64 {%0, %1}, %2;" : "=r"(lo), "=r"(hi) : "l"(acc0));
            s0 = __uint_as_float(lo) + __uint_as_float(hi);
            asm("mov.b64 {%0, %1}, %2;" : "=r"(lo), "=r"(hi) : "l"(acc1));
            s1 = __uint_as_float(lo) + __uint_as_float(hi);
        }

        float2 hn2;
        {
            float x, u;
            x = s0 + zg2.x; u = 1.f / (1.f + __expf(-x)); hn2.x = u * hp2.x + (1.f - u) * zv2.x;
            x = s1 + zg2.y; u = 1.f / (1.f + __expf(-x)); hn2.y = u * hp2.y + (1.f - u) * zv2.y;
        }
        *(float2*)(hn + (size_t)b * HH + jbase + j0) = hn2;

        // emit bf16 hi|lo for the output GEMM
        {
            __nv_bfloat162 hi2, lo2;
            hi2.x = __float2bfloat16(hn2.x); hi2.y = __float2bfloat16(hn2.y);
            lo2.x = __float2bfloat16(hn2.x - __bfloat162float(hi2.x));
            lo2.y = __float2bfloat16(hn2.y - __bfloat162float(hi2.y));
            __nv_bfloat16* srow = g_hs2 + ((size_t)t * BB + b) * 2048;
            *(__nv_bfloat162*)(srow + jbase + j0)        = hi2;
            *(__nv_bfloat162*)(srow + 1024 + jbase + j0) = lo2;
        }
        if (t == TT - 1)
            *(float2*)(out_hfinal + (size_t)b * HH + jbase + j0) = hn2;

        grid_sync((unsigned)t + 2);
    }

    __syncthreads();
    if (tid == 0) {
        const unsigned r2 = atomicAdd(&g_exit, 1u);
        if (r2 == NBLK - 1) { g_bar = 0u; g_exit = 0u; __threadfence(); }
    }
}

// ============================ kernel_launch ================================
extern "C" void kernel_launch(void* const* d_in, const int* in_sizes, int n_in,
                              void* d_out, int out_size)
{
    (void)in_sizes; (void)n_in; (void)out_size;
    const float* inputs = (const float*)d_in[0];   // [B][T][I]
    const float* h0     = (const float*)d_in[1];   // [B][H]
    const float* W_in   = (const float*)d_in[2];   // [H][I]
    const float* b_in   = (const float*)d_in[3];   // [H]
    const float* W_gate = (const float*)d_in[4];   // [H][2H]
    const float* b_gate = (const float*)d_in[5];   // [H]
    const float* W_out  = (const float*)d_in[6];   // [O][H]
    const float* b_out  = (const float*)d_in[7];   // [O]
    float* out = (float*)d_out;                    // outs [B][T][O] ++ h_final [B][H]

    void *zp, *zgp, *z2p, *hs2p, *in2p, *w1p, *w2p, *w3p;
    cudaGetSymbolAddress(&zp,   g_z);
    cudaGetSymbolAddress(&zgp,  g_zg);
    cudaGetSymbolAddress(&z2p,  g_z2);
    cudaGetSymbolAddress(&hs2p, g_hs2);
    cudaGetSymbolAddress(&in2p, g_in2);
    cudaGetSymbolAddress(&w1p,  g_Win2);
    cudaGetSymbolAddress(&w2p,  g_Wgz2);
    cudaGetSymbolAddress(&w3p,  g_Wout2);
    float* z  = (float*)zp;
    float* zg = (float*)zgp;
    __nv_bfloat16* z2   = (__nv_bfloat16*)z2p;
    __nv_bfloat16* hs2  = (__nv_bfloat16*)hs2p;
    __nv_bfloat16* in2  = (__nv_bfloat16*)in2p;
    __nv_bfloat16* Win2 = (__nv_bfloat16*)w1p;
    __nv_bfloat16* Wgz2 = (__nv_bfloat16*)w2p;
    __nv_bfloat16* Wout2= (__nv_bfloat16*)w3p;

    cudaFuncSetAttribute(gemm_tc<0, true>,  cudaFuncAttributeMaxDynamicSharedMemorySize, GEMM_SMEM);
    cudaFuncSetAttribute(gemm_tc<1, false>, cudaFuncAttributeMaxDynamicSharedMemorySize, GEMM_SMEM);
    cudaFuncSetAttribute(gemm_tc<2, false>, cudaFuncAttributeMaxDynamicSharedMemorySize, GEMM_SMEM);
    cudaFuncSetAttribute(scan_kernel, cudaFuncAttributeMaxDynamicSharedMemorySize, SCAN_SMEM);

    const int M = TT * BB;

    // pack weights + inputs into bf16 hi|lo
    pack_split<<<256,  256>>>(W_in,  Win2,  II, II,     0,  (long)HH * II);
    pack_split<<<256,  256>>>(W_gate,Wgz2,  HH, 2 * HH, HH, (long)HH * HH);
    pack_split<<<256,  256>>>(W_out, Wout2, HH, HH,     0,  (long)OO * HH);
    pack_split<<<2048, 256>>>(inputs,in2,   II, II,     0,  (long)BB * TT * II);

    // K1: z = inputs @ W_in^T + b_in  (emit z fp32 + z2 bf16 split)
    {
        dim3 grid(HH / 128, M / 128);
        gemm_tc<0, true><<<grid, 256, GEMM_SMEM>>>(in2, Win2, b_in, z, z2, 2 * II, HH, II / 32);
    }
    // K2: zg = z @ Wg_z^T + b_gate
    {
        dim3 grid(HH / 128, M / 128);
        gemm_tc<1, false><<<grid, 256, GEMM_SMEM>>>(z2, Wgz2, b_gate, zg, nullptr, 2 * HH, HH, HH / 32);
    }
    // K3: sequential scan (writes hs2 bf16 split + h_final)
    scan_kernel<<<NBLK, SCTH, SCAN_SMEM>>>(W_gate, h0, out + (size_t)BB * TT * OO);

    // K4: outs = hs @ W_out^T + b_out
    {
        dim3 grid(OO / 128, M / 128);
        gemm_tc<2, false><<<grid, 256, GEMM_SMEM>>>(hs2, Wout2, b_out, out, nullptr, 2 * HH, OO, HH / 32);
    }
}